// round 7
// baseline (speedup 1.0000x reference)
#include <cuda_runtime.h>
#include <cuda_fp16.h>
#include <cstdint>

// Problem constants: B=16, C=128, N=M=2048
#define B_  16
#define C_  128
#define N_  2048
#define K2F  14.4269504089f    // 10 * log2(e)  (SCALE folded into log2 domain)
#define LN2F 0.69314718055995f

#define NTILE   256            // n rows per CTA; 32 per warp (2 x m16 blocks)
#define MCHUNK  32
#define NCHUNKS 64
#define THREADS 256
#define NCTAS   128            // grid 8 x 16

// SMEM u32 layout. B double-buffers alias the A-stage region.
#define APAD   264             // A-stage: [64 kpair][APAD]
#define ASTAGE (64 * APAD)     // 16896 u32
#define BP     40              // B buffer row stride (conflict-free frags)
#define BBUF   (64 * BP)       // 2560 u32 per buffer (x2 aliased into A-stage)
#define POSU   ASTAGE          // posv[256] floats
#define FLGU   (POSU + 256)
#define SMEMU  (FLGU + 4)

__device__ float g_partial[NCTAS];
__device__ unsigned int g_count;   // zero-init; reset by last CTA each run

__device__ __forceinline__ float ex2f(float x) {
    float y;
    asm("ex2.approx.ftz.f32 %0, %1;" : "=f"(y) : "f"(x));
    return y;
}
__device__ __forceinline__ float lg2f(float x) {
    float y;
    asm("lg2.approx.ftz.f32 %0, %1;" : "=f"(y) : "f"(x));
    return y;
}
__device__ __forceinline__ void mma_f16(float* c, const uint32_t* a,
                                        uint32_t b0, uint32_t b1) {
    asm volatile("mma.sync.aligned.m16n8k16.row.col.f32.f16.f16.f32 "
                 "{%0,%1,%2,%3}, {%4,%5,%6,%7}, {%8,%9}, {%0,%1,%2,%3};"
                 : "+f"(c[0]), "+f"(c[1]), "+f"(c[2]), "+f"(c[3])
                 : "r"(a[0]), "r"(a[1]), "r"(a[2]), "r"(a[3]), "r"(b0), "r"(b1));
}

extern __shared__ uint32_t smu[];

__global__ void __launch_bounds__(THREADS, 1)
patchnce_main(const float* __restrict__ q,
              const float* __restrict__ p,
              const float* __restrict__ neg,
              float* __restrict__ out) {
    const int tid  = threadIdx.x;
    const int w    = tid >> 5;
    const int lane = tid & 31;
    const int g    = lane >> 2;
    const int t4   = lane & 3;
    const int b    = blockIdx.y;
    const int n0   = blockIdx.x * NTILE;

    float* posv = (float*)&smu[POSU];
    int*   flag = (int*)&smu[FLGU];

    // ------ Phase 1: stage Q tile (256 rows) as f16x2 kpairs + positive dot
    {
        const float* qb = q + (size_t)b * C_ * N_ + n0 + tid;
        const float* pb = p + (size_t)b * C_ * N_ + n0 + tid;
        float pd = 0.f;
#pragma unroll 8
        for (int kp = 0; kp < 64; kp++) {
            float q0 = qb[(size_t)(2 * kp)     * N_];
            float q1 = qb[(size_t)(2 * kp + 1) * N_];
            float p0 = pb[(size_t)(2 * kp)     * N_];
            float p1 = pb[(size_t)(2 * kp + 1) * N_];
            pd = fmaf(q0, p0, fmaf(q1, p1, pd));
            __half2 h = __floats2half2_rn(q0, q1);
            smu[kp * APAD + tid] = *(uint32_t*)&h;
        }
        posv[tid] = pd;
    }
    __syncthreads();

    // ------ Phase 2: A fragments (2 m16 blocks x 8 ksteps) -> 64 registers
    uint32_t afr[64];
#pragma unroll
    for (int mblk = 0; mblk < 2; mblk++) {
        const int rb = w * 32 + mblk * 16 + g;
#pragma unroll
        for (int ks = 0; ks < 8; ks++) {
            uint32_t* a = afr + mblk * 32 + ks * 4;
            a[0] = smu[(ks * 8 + t4)     * APAD + rb];
            a[1] = smu[(ks * 8 + t4)     * APAD + rb + 8];
            a[2] = smu[(ks * 8 + t4 + 4) * APAD + rb];
            a[3] = smu[(ks * 8 + t4 + 4) * APAD + rb + 8];
        }
    }
    __syncthreads();   // A-stage region becomes the B double-buffer

    // ------ Phase 3: stream Neg chunks, HMMA + base-2 online softmax -------
    const float* nb = neg + (size_t)b * C_ * N_;
    const int kp0 = tid >> 3;
    const int mq  = tid & 7;

    float4 pr[4];
    auto loadB = [&](int ch) {
        const float* s = nb + ch * MCHUNK + mq * 4;
#pragma unroll
        for (int i = 0; i < 2; i++) {
            const int kp = kp0 + i * 32;
            pr[i * 2 + 0] = *(const float4*)(s + (size_t)(2 * kp)     * N_);
            pr[i * 2 + 1] = *(const float4*)(s + (size_t)(2 * kp + 1) * N_);
        }
    };
    auto storeB = [&](int buf) {
        uint32_t* bb = smu + buf * BBUF;
#pragma unroll
        for (int i = 0; i < 2; i++) {
            const int kp = kp0 + i * 32;
            __half2 h0 = __floats2half2_rn(pr[i*2].x, pr[i*2+1].x);
            __half2 h1 = __floats2half2_rn(pr[i*2].y, pr[i*2+1].y);
            __half2 h2 = __floats2half2_rn(pr[i*2].z, pr[i*2+1].z);
            __half2 h3 = __floats2half2_rn(pr[i*2].w, pr[i*2+1].w);
            uint4 v = { *(uint32_t*)&h0, *(uint32_t*)&h1,
                        *(uint32_t*)&h2, *(uint32_t*)&h3 };
            *(uint4*)&bb[kp * BP + mq * 4] = v;
        }
    };

    float rmax2[4], rsum[4];
#pragma unroll
    for (int s = 0; s < 4; s++) { rmax2[s] = -1e30f; rsum[s] = 0.f; }

    loadB(0); storeB(0); loadB(1);
    __syncthreads();

    for (int ch = 0; ch < NCHUNKS; ch++) {
        if (ch + 1 < NCHUNKS) storeB((ch + 1) & 1);
        if (ch + 2 < NCHUNKS) loadB(ch + 2);

        const uint32_t* bb = smu + (ch & 1) * BBUF;
        float acc[4][2][4];      // [grp][mblk][c]
#pragma unroll
        for (int i = 0; i < 4; i++)
#pragma unroll
            for (int m = 0; m < 2; m++)
#pragma unroll
                for (int j = 0; j < 4; j++) acc[i][m][j] = 0.f;

#pragma unroll
        for (int ks = 0; ks < 8; ks++) {
            uint32_t b0[4], b1[4];
#pragma unroll
            for (int grp = 0; grp < 4; grp++) {
                b0[grp] = bb[(ks * 8 + t4)     * BP + grp * 8 + g];
                b1[grp] = bb[(ks * 8 + t4 + 4) * BP + grp * 8 + g];
            }
#pragma unroll
            for (int grp = 0; grp < 4; grp++) {
                mma_f16(acc[grp][0], afr + ks * 4,      b0[grp], b1[grp]);
                mma_f16(acc[grp][1], afr + 32 + ks * 4, b0[grp], b1[grp]);
            }
        }

        // base-2 online softmax: 4 row-slots = (mblk, half)
#pragma unroll
        for (int mblk = 0; mblk < 2; mblk++) {
#pragma unroll
            for (int h = 0; h < 2; h++) {
                const int s = mblk * 2 + h;
                float v0 = acc[0][mblk][h*2], v1 = acc[0][mblk][h*2+1];
                float v2 = acc[1][mblk][h*2], v3 = acc[1][mblk][h*2+1];
                float v4 = acc[2][mblk][h*2], v5 = acc[2][mblk][h*2+1];
                float v6 = acc[3][mblk][h*2], v7 = acc[3][mblk][h*2+1];
                float vm = fmaxf(fmaxf(fmaxf(v0, v1), fmaxf(v2, v3)),
                                 fmaxf(fmaxf(v4, v5), fmaxf(v6, v7)));
                float lm2 = vm * K2F;
                if (lm2 > rmax2[s]) { rsum[s] *= ex2f(rmax2[s] - lm2); rmax2[s] = lm2; }
                float r = rmax2[s];
                float e0 = ex2f(fmaf(v0, K2F, -r)), e1 = ex2f(fmaf(v1, K2F, -r));
                float e2 = ex2f(fmaf(v2, K2F, -r)), e3 = ex2f(fmaf(v3, K2F, -r));
                float e4 = ex2f(fmaf(v4, K2F, -r)), e5 = ex2f(fmaf(v5, K2F, -r));
                float e6 = ex2f(fmaf(v6, K2F, -r)), e7 = ex2f(fmaf(v7, K2F, -r));
                rsum[s] += ((e0 + e1) + (e2 + e3)) + ((e4 + e5) + (e6 + e7));
            }
        }
        __syncthreads();
    }

    // ------ Combine the 4 lanes (t4) sharing each row ----------------------
#pragma unroll
    for (int s = 0; s < 4; s++) {
#pragma unroll
        for (int d = 1; d <= 2; d <<= 1) {
            float om = __shfl_xor_sync(0xFFFFFFFFu, rmax2[s], d);
            float os = __shfl_xor_sync(0xFFFFFFFFu, rsum[s], d);
            float nm = fmaxf(rmax2[s], om);
            rsum[s] = rsum[s] * ex2f(rmax2[s] - nm) + os * ex2f(om - nm);
            rmax2[s] = nm;
        }
    }

    float loss = 0.f;
    if (t4 == 0) {
#pragma unroll
        for (int mblk = 0; mblk < 2; mblk++) {
#pragma unroll
            for (int h = 0; h < 2; h++) {
                const int s = mblk * 2 + h;
                const int r = w * 32 + mblk * 16 + h * 8 + g;
                float lp2 = posv[r] * K2F;
                float M2 = fmaxf(rmax2[s], lp2);
                float S2 = rsum[s] * ex2f(rmax2[s] - M2) + ex2f(lp2 - M2);
                loss += (M2 + lg2f(S2) - lp2) * LN2F;
            }
        }
    }

    // ------ Deterministic per-CTA reduction (reuse B-buffer smem) ----------
    __syncthreads();
    float* tmp = (float*)smu;
    tmp[tid] = loss;
    __syncthreads();
    for (int o = 128; o > 0; o >>= 1) {
        if (tid < o) tmp[tid] += tmp[tid + o];
        __syncthreads();
    }

    // ------ Cross-CTA fold: last CTA finishes ------------------------------
    const int cta = blockIdx.y * 8 + blockIdx.x;
    if (tid == 0) {
        g_partial[cta] = tmp[0];
        __threadfence();
        unsigned v = atomicAdd(&g_count, 1u);
        *flag = (v == NCTAS - 1) ? 1 : 0;
    }
    __syncthreads();
    if (*flag) {
        __threadfence();
        tmp[tid] = (tid < NCTAS) ? g_partial[tid] : 0.f;
        __syncthreads();
        for (int o = 64; o > 0; o >>= 1) {
            if (tid < o) tmp[tid] += tmp[tid + o];
            __syncthreads();
        }
        if (tid == 0) {
            out[0] = tmp[0] / (float)(B_ * N_);
            g_count = 0;
        }
    }
}

// ---------------------------------------------------------------------------
extern "C" void kernel_launch(void* const* d_in, const int* in_sizes, int n_in,
                              void* d_out, int out_size) {
    const float* q   = (const float*)d_in[0];
    const float* pos = (const float*)d_in[1];
    const float* neg = (const float*)d_in[2];
    float* out = (float*)d_out;

    cudaFuncSetAttribute(patchnce_main,
                         cudaFuncAttributeMaxDynamicSharedMemorySize,
                         SMEMU * sizeof(uint32_t));
    patchnce_main<<<dim3(8, 16), THREADS, SMEMU * sizeof(uint32_t)>>>(q, pos, neg, out);
}

// round 9
// speedup vs baseline: 1.1098x; 1.1098x over previous
#include <cuda_runtime.h>
#include <cuda_fp16.h>
#include <cstdint>

// Problem constants: B=16, C=128, N=M=2048
#define B_  16
#define C_  128
#define N_  2048
#define K2F  14.4269504089f    // 10 * log2(e)
#define LN2F 0.69314718055995f

#define NTILE   256
#define MCHUNK  32
#define NCHUNKS 64
#define THREADS 256
#define NCTAS   128            // grid 8 x 16

#define APAD   264
#define ASTAGE (64 * APAD)
#define BP     40
#define BBUF   (64 * BP)
#define POSU   ASTAGE
#define FLGU   (POSU + 256)
#define SMEMU  (FLGU + 4)

__device__ float g_partial[NCTAS];
__device__ unsigned int g_count;

__device__ __forceinline__ float ex2f(float x) {
    float y;
    asm("ex2.approx.ftz.f32 %0, %1;" : "=f"(y) : "f"(x));
    return y;
}
__device__ __forceinline__ float lg2f(float x) {
    float y;
    asm("lg2.approx.ftz.f32 %0, %1;" : "=f"(y) : "f"(x));
    return y;
}
__device__ __forceinline__ void mma_f16(float* c, const uint32_t* a,
                                        uint32_t b0, uint32_t b1) {
    asm volatile("mma.sync.aligned.m16n8k16.row.col.f32.f16.f16.f32 "
                 "{%0,%1,%2,%3}, {%4,%5,%6,%7}, {%8,%9}, {%0,%1,%2,%3};"
                 : "+f"(c[0]), "+f"(c[1]), "+f"(c[2]), "+f"(c[3])
                 : "r"(a[0]), "r"(a[1]), "r"(a[2]), "r"(a[3]), "r"(b0), "r"(b1));
}

extern __shared__ uint32_t smu[];

__global__ void __launch_bounds__(THREADS, 1)
patchnce_main(const float* __restrict__ q,
              const float* __restrict__ p,
              const float* __restrict__ neg,
              float* __restrict__ out) {
    const int tid  = threadIdx.x;
    const int w    = tid >> 5;
    const int lane = tid & 31;
    const int g    = lane >> 2;
    const int t4   = lane & 3;
    const int b    = blockIdx.y;
    const int n0   = blockIdx.x * NTILE;

    float* posv = (float*)&smu[POSU];
    int*   flag = (int*)&smu[FLGU];

    // ------ Phase 1: stage Q tile as f16x2 kpairs + positive dot -----------
    {
        const float* qb = q + (size_t)b * C_ * N_ + n0 + tid;
        const float* pb = p + (size_t)b * C_ * N_ + n0 + tid;
        float pd = 0.f;
#pragma unroll 8
        for (int kp = 0; kp < 64; kp++) {
            float q0 = qb[(size_t)(2 * kp)     * N_];
            float q1 = qb[(size_t)(2 * kp + 1) * N_];
            float p0 = pb[(size_t)(2 * kp)     * N_];
            float p1 = pb[(size_t)(2 * kp + 1) * N_];
            pd = fmaf(q0, p0, fmaf(q1, p1, pd));
            __half2 h = __floats2half2_rn(q0, q1);
            smu[kp * APAD + tid] = *(uint32_t*)&h;
        }
        posv[tid] = pd;
    }
    __syncthreads();

    // ------ Phase 2: A fragments -> 64 registers ---------------------------
    uint32_t afr[64];
#pragma unroll
    for (int mblk = 0; mblk < 2; mblk++) {
        const int rb = w * 32 + mblk * 16 + g;
#pragma unroll
        for (int ks = 0; ks < 8; ks++) {
            uint32_t* a = afr + mblk * 32 + ks * 4;
            a[0] = smu[(ks * 8 + t4)     * APAD + rb];
            a[1] = smu[(ks * 8 + t4)     * APAD + rb + 8];
            a[2] = smu[(ks * 8 + t4 + 4) * APAD + rb];
            a[3] = smu[(ks * 8 + t4 + 4) * APAD + rb + 8];
        }
    }
    __syncthreads();

    // ------ Phase 3: pipelined Neg streaming, HMMA || softmax --------------
    const float* nb = neg + (size_t)b * C_ * N_;
    const int kp0 = tid >> 3;
    const int mq  = tid & 7;

    float4 pr[4];
    auto loadB = [&](int ch) {
        const float* s = nb + ch * MCHUNK + mq * 4;
#pragma unroll
        for (int i = 0; i < 2; i++) {
            const int kp = kp0 + i * 32;
            pr[i * 2 + 0] = *(const float4*)(s + (size_t)(2 * kp)     * N_);
            pr[i * 2 + 1] = *(const float4*)(s + (size_t)(2 * kp + 1) * N_);
        }
    };
    auto storeB = [&](int buf) {
        uint32_t* bb = smu + buf * BBUF;
#pragma unroll
        for (int i = 0; i < 2; i++) {
            const int kp = kp0 + i * 32;
            __half2 h0 = __floats2half2_rn(pr[i*2].x, pr[i*2+1].x);
            __half2 h1 = __floats2half2_rn(pr[i*2].y, pr[i*2+1].y);
            __half2 h2 = __floats2half2_rn(pr[i*2].z, pr[i*2+1].z);
            __half2 h3 = __floats2half2_rn(pr[i*2].w, pr[i*2+1].w);
            uint4 v = { *(uint32_t*)&h0, *(uint32_t*)&h1,
                        *(uint32_t*)&h2, *(uint32_t*)&h3 };
            *(uint4*)&bb[kp * BP + mq * 4] = v;
        }
    };

    float rmax2[4], rsum[4];
#pragma unroll
    for (int s = 0; s < 4; s++) { rmax2[s] = -1e30f; rsum[s] = 0.f; }

    float acc0[4][2][4], acc1[4][2][4];

    auto mma_chunk = [&](int buf, float (&acc)[4][2][4]) {
        const uint32_t* bb = smu + buf * BBUF;
#pragma unroll
        for (int i = 0; i < 4; i++)
#pragma unroll
            for (int m = 0; m < 2; m++)
#pragma unroll
                for (int j = 0; j < 4; j++) acc[i][m][j] = 0.f;
#pragma unroll
        for (int ks = 0; ks < 8; ks++) {
            uint32_t b0[4], b1[4];
#pragma unroll
            for (int grp = 0; grp < 4; grp++) {
                b0[grp] = bb[(ks * 8 + t4)     * BP + grp * 8 + g];
                b1[grp] = bb[(ks * 8 + t4 + 4) * BP + grp * 8 + g];
            }
#pragma unroll
            for (int grp = 0; grp < 4; grp++) {
                mma_f16(acc[grp][0], afr + ks * 4,      b0[grp], b1[grp]);
                mma_f16(acc[grp][1], afr + 32 + ks * 4, b0[grp], b1[grp]);
            }
        }
    };

    auto softmax_acc = [&](float (&acc)[4][2][4]) {
#pragma unroll
        for (int mblk = 0; mblk < 2; mblk++) {
#pragma unroll
            for (int h = 0; h < 2; h++) {
                const int s = mblk * 2 + h;
                float v0 = acc[0][mblk][h*2], v1 = acc[0][mblk][h*2+1];
                float v2 = acc[1][mblk][h*2], v3 = acc[1][mblk][h*2+1];
                float v4 = acc[2][mblk][h*2], v5 = acc[2][mblk][h*2+1];
                float v6 = acc[3][mblk][h*2], v7 = acc[3][mblk][h*2+1];
                float vm = fmaxf(fmaxf(fmaxf(v0, v1), fmaxf(v2, v3)),
                                 fmaxf(fmaxf(v4, v5), fmaxf(v6, v7)));
                float lm2 = vm * K2F;
                if (lm2 > rmax2[s]) { rsum[s] *= ex2f(rmax2[s] - lm2); rmax2[s] = lm2; }
                float r = rmax2[s];
                float e0 = ex2f(fmaf(v0, K2F, -r)), e1 = ex2f(fmaf(v1, K2F, -r));
                float e2 = ex2f(fmaf(v2, K2F, -r)), e3 = ex2f(fmaf(v3, K2F, -r));
                float e4 = ex2f(fmaf(v4, K2F, -r)), e5 = ex2f(fmaf(v5, K2F, -r));
                float e6 = ex2f(fmaf(v6, K2F, -r)), e7 = ex2f(fmaf(v7, K2F, -r));
                rsum[s] += ((e0 + e1) + (e2 + e3)) + ((e4 + e5) + (e6 + e7));
            }
        }
    };

    // Prologue: pr<-chunk0, smem buf0<-chunk0, pr<-chunk1, MMA chunk0.
    loadB(0); storeB(0); loadB(1);
    __syncthreads();
    mma_chunk(0, acc0);

    // Pipelined steady state: softmax(c) overlaps MMA(c+1).
#pragma unroll 1
    for (int ch = 0; ch < NCHUNKS; ch += 2) {
        if (ch + 1 < NCHUNKS) {
            storeB(1);                          // stage odd chunk ch+1
            if (ch + 2 < NCHUNKS) loadB(ch + 2);
            __syncthreads();
            mma_chunk(1, acc1);                 // tensor work for ch+1 ...
        }
        softmax_acc(acc0);                      // ... overlaps MUFU for ch

        if (ch + 2 < NCHUNKS) {
            storeB(0);                          // stage even chunk ch+2
            if (ch + 3 < NCHUNKS) loadB(ch + 3);
            __syncthreads();
            mma_chunk(0, acc0);                 // tensor for ch+2 ...
        }
        if (ch + 1 < NCHUNKS) softmax_acc(acc1);// ... overlaps MUFU for ch+1
    }

    // ------ Combine the 4 lanes (t4) sharing each row ----------------------
#pragma unroll
    for (int s = 0; s < 4; s++) {
#pragma unroll
        for (int d = 1; d <= 2; d <<= 1) {
            float om = __shfl_xor_sync(0xFFFFFFFFu, rmax2[s], d);
            float os = __shfl_xor_sync(0xFFFFFFFFu, rsum[s], d);
            float nm = fmaxf(rmax2[s], om);
            rsum[s] = rsum[s] * ex2f(rmax2[s] - nm) + os * ex2f(om - nm);
            rmax2[s] = nm;
        }
    }

    float loss = 0.f;
    if (t4 == 0) {
#pragma unroll
        for (int mblk = 0; mblk < 2; mblk++) {
#pragma unroll
            for (int h = 0; h < 2; h++) {
                const int s = mblk * 2 + h;
                const int r = w * 32 + mblk * 16 + h * 8 + g;
                float lp2 = posv[r] * K2F;
                float M2 = fmaxf(rmax2[s], lp2);
                float S2 = rsum[s] * ex2f(rmax2[s] - M2) + ex2f(lp2 - M2);
                loss += (M2 + lg2f(S2) - lp2) * LN2F;
            }
        }
    }

    // ------ Deterministic per-CTA reduction --------------------------------
    __syncthreads();
    float* tmp = (float*)smu;
    tmp[tid] = loss;
    __syncthreads();
    for (int o = 128; o > 0; o >>= 1) {
        if (tid < o) tmp[tid] += tmp[tid + o];
        __syncthreads();
    }

    // ------ Cross-CTA fold: last CTA finishes ------------------------------
    const int cta = blockIdx.y * 8 + blockIdx.x;
    if (tid == 0) {
        g_partial[cta] = tmp[0];
        __threadfence();
        unsigned v = atomicAdd(&g_count, 1u);
        *flag = (v == NCTAS - 1) ? 1 : 0;
    }
    __syncthreads();
    if (*flag) {
        __threadfence();
        tmp[tid] = (tid < NCTAS) ? g_partial[tid] : 0.f;
        __syncthreads();
        for (int o = 64; o > 0; o >>= 1) {
            if (tid < o) tmp[tid] += tmp[tid + o];
            __syncthreads();
        }
        if (tid == 0) {
            out[0] = tmp[0] / (float)(B_ * N_);
            g_count = 0;
        }
    }
}

// ---------------------------------------------------------------------------
extern "C" void kernel_launch(void* const* d_in, const int* in_sizes, int n_in,
                              void* d_out, int out_size) {
    const float* q   = (const float*)d_in[0];
    const float* pos = (const float*)d_in[1];
    const float* neg = (const float*)d_in[2];
    float* out = (float*)d_out;

    cudaFuncSetAttribute(patchnce_main,
                         cudaFuncAttributeMaxDynamicSharedMemorySize,
                         SMEMU * sizeof(uint32_t));
    patchnce_main<<<dim3(8, 16), THREADS, SMEMU * sizeof(uint32_t)>>>(q, pos, neg, out);
}

// round 10
// speedup vs baseline: 1.1377x; 1.0251x over previous
#include <cuda_runtime.h>
#include <cuda_fp16.h>
#include <cstdint>

// Problem constants: B=16, C=128, N=M=2048
#define B_  16
#define C_  128
#define N_  2048
#define K2F  14.4269504089f    // 10 * log2(e)
#define LN2F 0.69314718055995f

#define NTILE   256
#define MCHUNK  32
#define NCHUNKS 64
#define THREADS 256
#define NCTAS   128            // grid 8 x 16

#define APAD   264
#define ASTAGE (64 * APAD)
#define BP     40
#define BBUF   (64 * BP)
#define POSU   ASTAGE
#define FLGU   (POSU + 256)
#define SMEMU  (FLGU + 4)

__device__ float g_partial[NCTAS];
__device__ unsigned int g_count;

__device__ __forceinline__ float ex2f(float x) {
    float y;
    asm("ex2.approx.ftz.f32 %0, %1;" : "=f"(y) : "f"(x));
    return y;
}
__device__ __forceinline__ float lg2f(float x) {
    float y;
    asm("lg2.approx.ftz.f32 %0, %1;" : "=f"(y) : "f"(x));
    return y;
}
__device__ __forceinline__ void mma_f16(float* c, const uint32_t* a,
                                        uint32_t b0, uint32_t b1) {
    asm volatile("mma.sync.aligned.m16n8k16.row.col.f32.f16.f16.f32 "
                 "{%0,%1,%2,%3}, {%4,%5,%6,%7}, {%8,%9}, {%0,%1,%2,%3};"
                 : "+f"(c[0]), "+f"(c[1]), "+f"(c[2]), "+f"(c[3])
                 : "r"(a[0]), "r"(a[1]), "r"(a[2]), "r"(a[3]), "r"(b0), "r"(b1));
}

extern __shared__ uint32_t smu[];

__global__ void __launch_bounds__(THREADS, 1)
patchnce_main(const float* __restrict__ q,
              const float* __restrict__ p,
              const float* __restrict__ neg,
              float* __restrict__ out) {
    const int tid  = threadIdx.x;
    const int w    = tid >> 5;
    const int lane = tid & 31;
    const int g    = lane >> 2;
    const int t4   = lane & 3;
    const int b    = blockIdx.y;
    const int n0   = blockIdx.x * NTILE;

    float* posv = (float*)&smu[POSU];
    int*   flag = (int*)&smu[FLGU];

    // ------ Phase 1: stage Q tile as f16x2 kpairs + positive dot -----------
    {
        const float* qb = q + (size_t)b * C_ * N_ + n0 + tid;
        const float* pb = p + (size_t)b * C_ * N_ + n0 + tid;
        float pd = 0.f;
#pragma unroll 8
        for (int kp = 0; kp < 64; kp++) {
            float q0 = qb[(size_t)(2 * kp)     * N_];
            float q1 = qb[(size_t)(2 * kp + 1) * N_];
            float p0 = pb[(size_t)(2 * kp)     * N_];
            float p1 = pb[(size_t)(2 * kp + 1) * N_];
            pd = fmaf(q0, p0, fmaf(q1, p1, pd));
            __half2 h = __floats2half2_rn(q0, q1);
            smu[kp * APAD + tid] = *(uint32_t*)&h;
        }
        posv[tid] = pd;
    }
    __syncthreads();

    // ------ Phase 2: A fragments -> 64 registers ---------------------------
    uint32_t afr[64];
#pragma unroll
    for (int mblk = 0; mblk < 2; mblk++) {
        const int rb = w * 32 + mblk * 16 + g;
#pragma unroll
        for (int ks = 0; ks < 8; ks++) {
            uint32_t* a = afr + mblk * 32 + ks * 4;
            a[0] = smu[(ks * 8 + t4)     * APAD + rb];
            a[1] = smu[(ks * 8 + t4)     * APAD + rb + 8];
            a[2] = smu[(ks * 8 + t4 + 4) * APAD + rb];
            a[3] = smu[(ks * 8 + t4 + 4) * APAD + rb + 8];
        }
    }
    __syncthreads();

    // ------ Phase 3: fused pipeline --------------------------------------
    const float* nb = neg + (size_t)b * C_ * N_;
    const int kp0 = tid >> 3;
    const int mq  = tid & 7;

    float4 pr[4];
    auto loadB = [&](int ch) {
        const float* s = nb + ch * MCHUNK + mq * 4;
#pragma unroll
        for (int i = 0; i < 2; i++) {
            const int kp = kp0 + i * 32;
            pr[i * 2 + 0] = *(const float4*)(s + (size_t)(2 * kp)     * N_);
            pr[i * 2 + 1] = *(const float4*)(s + (size_t)(2 * kp + 1) * N_);
        }
    };
    auto storeB = [&](int buf) {
        uint32_t* bb = smu + buf * BBUF;
#pragma unroll
        for (int i = 0; i < 2; i++) {
            const int kp = kp0 + i * 32;
            __half2 h0 = __floats2half2_rn(pr[i*2].x, pr[i*2+1].x);
            __half2 h1 = __floats2half2_rn(pr[i*2].y, pr[i*2+1].y);
            __half2 h2 = __floats2half2_rn(pr[i*2].z, pr[i*2+1].z);
            __half2 h3 = __floats2half2_rn(pr[i*2].w, pr[i*2+1].w);
            uint4 v = { *(uint32_t*)&h0, *(uint32_t*)&h1,
                        *(uint32_t*)&h2, *(uint32_t*)&h3 };
            *(uint4*)&bb[kp * BP + mq * 4] = v;
        }
    };

    float rmax2[4], rsum[4];
#pragma unroll
    for (int s = 0; s < 4; s++) { rmax2[s] = -1e30f; rsum[s] = 0.f; }

    float acc0[4][2][4], acc1[4][2][4];

    // one softmax slot: branchless rescale + f16x2 ex2
    auto softmax_slot = [&](float (&acc)[4][2][4], int s) {
        const int mblk = s >> 1, h = s & 1;
        float v0 = acc[0][mblk][h*2], v1 = acc[0][mblk][h*2+1];
        float v2 = acc[1][mblk][h*2], v3 = acc[1][mblk][h*2+1];
        float v4 = acc[2][mblk][h*2], v5 = acc[2][mblk][h*2+1];
        float v6 = acc[3][mblk][h*2], v7 = acc[3][mblk][h*2+1];
        float vm = fmaxf(fmaxf(fmaxf(v0, v1), fmaxf(v2, v3)),
                         fmaxf(fmaxf(v4, v5), fmaxf(v6, v7)));
        float nm = fmaxf(rmax2[s], vm * K2F);
        rsum[s] *= ex2f(rmax2[s] - nm);
        rmax2[s] = nm;
        const float r = nm;
        __half2 e01 = h2exp2(__floats2half2_rn(fmaf(v0, K2F, -r), fmaf(v1, K2F, -r)));
        __half2 e23 = h2exp2(__floats2half2_rn(fmaf(v2, K2F, -r), fmaf(v3, K2F, -r)));
        __half2 e45 = h2exp2(__floats2half2_rn(fmaf(v4, K2F, -r), fmaf(v5, K2F, -r)));
        __half2 e67 = h2exp2(__floats2half2_rn(fmaf(v6, K2F, -r), fmaf(v7, K2F, -r)));
        __half2 st = __hadd2(__hadd2(e01, e23), __hadd2(e45, e67));
        float2 f = __half22float2(st);
        rsum[s] += f.x + f.y;
    };
    auto softmax_full = [&](float (&acc)[4][2][4]) {
#pragma unroll
        for (int s = 0; s < 4; s++) softmax_slot(acc, s);
    };

    // fused: MMA of chunk in `buf` into aN, interleaving softmax of aO.
    // B fragments register-prefetched one ks-step ahead.
    auto fused = [&](int buf, float (&aN)[4][2][4], float (&aO)[4][2][4],
                     bool doSoft) {
        const uint32_t* bb = smu + buf * BBUF;
#pragma unroll
        for (int i = 0; i < 4; i++)
#pragma unroll
            for (int m = 0; m < 2; m++)
#pragma unroll
                for (int j = 0; j < 4; j++) aN[i][m][j] = 0.f;

        uint32_t bc[8], bn[8];
#pragma unroll
        for (int grp = 0; grp < 4; grp++) {
            bc[grp]     = bb[t4 * BP + grp * 8 + g];
            bc[4 + grp] = bb[(t4 + 4) * BP + grp * 8 + g];
        }
#pragma unroll
        for (int ks = 0; ks < 8; ks++) {
            if (ks < 7) {
#pragma unroll
                for (int grp = 0; grp < 4; grp++) {
                    bn[grp]     = bb[((ks + 1) * 8 + t4)     * BP + grp * 8 + g];
                    bn[4 + grp] = bb[((ks + 1) * 8 + t4 + 4) * BP + grp * 8 + g];
                }
            }
#pragma unroll
            for (int grp = 0; grp < 4; grp++) {
                mma_f16(aN[grp][0], afr + ks * 4,      bc[grp], bc[4 + grp]);
                mma_f16(aN[grp][1], afr + 32 + ks * 4, bc[grp], bc[4 + grp]);
            }
            if (doSoft && (ks & 1)) softmax_slot(aO, ks >> 1);
#pragma unroll
            for (int i = 0; i < 8; i++) bc[i] = bn[i];
        }
    };

    // Prologue
    loadB(0); storeB(0); loadB(1);
    __syncthreads();
    fused(0, acc0, acc1, false);          // chunk 0 -> acc0

    // Steady state: fused(chunk c+1) interleaves softmax(chunk c)
#pragma unroll 1
    for (int ch = 0; ch < NCHUNKS; ch += 2) {
        if (ch + 1 < NCHUNKS) {
            storeB(1);
            if (ch + 2 < NCHUNKS) loadB(ch + 2);
            __syncthreads();
            fused(1, acc1, acc0, true);   // MMA ch+1, softmax ch
        } else {
            softmax_full(acc0);
        }
        if (ch + 2 < NCHUNKS) {
            storeB(0);
            if (ch + 3 < NCHUNKS) loadB(ch + 3);
            __syncthreads();
            fused(0, acc0, acc1, true);   // MMA ch+2, softmax ch+1
        } else if (ch + 1 < NCHUNKS) {
            softmax_full(acc1);           // final chunk
        }
    }

    // ------ Combine the 4 lanes (t4) sharing each row ----------------------
#pragma unroll
    for (int s = 0; s < 4; s++) {
#pragma unroll
        for (int d = 1; d <= 2; d <<= 1) {
            float om = __shfl_xor_sync(0xFFFFFFFFu, rmax2[s], d);
            float os = __shfl_xor_sync(0xFFFFFFFFu, rsum[s], d);
            float nm = fmaxf(rmax2[s], om);
            rsum[s] = rsum[s] * ex2f(rmax2[s] - nm) + os * ex2f(om - nm);
            rmax2[s] = nm;
        }
    }

    float loss = 0.f;
    if (t4 == 0) {
#pragma unroll
        for (int mblk = 0; mblk < 2; mblk++) {
#pragma unroll
            for (int h = 0; h < 2; h++) {
                const int s = mblk * 2 + h;
                const int r = w * 32 + mblk * 16 + h * 8 + g;
                float lp2 = posv[r] * K2F;
                float M2 = fmaxf(rmax2[s], lp2);
                float S2 = rsum[s] * ex2f(rmax2[s] - M2) + ex2f(lp2 - M2);
                loss += (M2 + lg2f(S2) - lp2) * LN2F;
            }
        }
    }

    // ------ Deterministic per-CTA reduction --------------------------------
    __syncthreads();
    float* tmp = (float*)smu;
    tmp[tid] = loss;
    __syncthreads();
    for (int o = 128; o > 0; o >>= 1) {
        if (tid < o) tmp[tid] += tmp[tid + o];
        __syncthreads();
    }

    // ------ Cross-CTA fold: last CTA finishes ------------------------------
    const int cta = blockIdx.y * 8 + blockIdx.x;
    if (tid == 0) {
        g_partial[cta] = tmp[0];
        __threadfence();
        unsigned v = atomicAdd(&g_count, 1u);
        *flag = (v == NCTAS - 1) ? 1 : 0;
    }
    __syncthreads();
    if (*flag) {
        __threadfence();
        tmp[tid] = (tid < NCTAS) ? g_partial[tid] : 0.f;
        __syncthreads();
        for (int o = 64; o > 0; o >>= 1) {
            if (tid < o) tmp[tid] += tmp[tid + o];
            __syncthreads();
        }
        if (tid == 0) {
            out[0] = tmp[0] / (float)(B_ * N_);
            g_count = 0;
        }
    }
}

// ---------------------------------------------------------------------------
extern "C" void kernel_launch(void* const* d_in, const int* in_sizes, int n_in,
                              void* d_out, int out_size) {
    const float* q   = (const float*)d_in[0];
    const float* pos = (const float*)d_in[1];
    const float* neg = (const float*)d_in[2];
    float* out = (float*)d_out;

    cudaFuncSetAttribute(patchnce_main,
                         cudaFuncAttributeMaxDynamicSharedMemorySize,
                         SMEMU * sizeof(uint32_t));
    patchnce_main<<<dim3(8, 16), THREADS, SMEMU * sizeof(uint32_t)>>>(q, pos, neg, out);
}